// round 1
// baseline (speedup 1.0000x reference)
#include <cuda_runtime.h>
#include <cuda_bf16.h>
#include <math.h>

// ---------------- problem constants ----------------
#define BATCH   8
#define NPTS    16384
#define NPOINT  1024
#define NSAMPLE 32
#define NTOT    (BATCH * NPOINT * NSAMPLE)   // 262144 rows through the MLP
#define C0      6
#define C1      64
#define C2      64
#define C3      128

// ---------------- device scratch (no allocations allowed) ----------------
__device__ int    g_fidx[BATCH * NPOINT];
__device__ float  g_feat0[(size_t)NTOT * C0];
__device__ float  g_act1[(size_t)NTOT * C1];
__device__ float  g_act2[(size_t)NTOT * C2];
__device__ float  g_act3[(size_t)NTOT * C3];
__device__ double g_sum[3 * 128];
__device__ double g_sq[3 * 128];
__device__ float  g_sA[3 * 128];
__device__ float  g_sB[3 * 128];

// ---------------- FPS: one block per batch ----------------
// distance array in dynamic shared (64KB), point coords in registers (16/thread)
__global__ __launch_bounds__(1024, 1)
void fps_kernel(const float* __restrict__ xyz, int* __restrict__ fidx,
                float* __restrict__ newxyz)
{
    extern __shared__ float sdist[];          // NPTS floats
    __shared__ unsigned long long swarp[32];
    __shared__ int sfar;

    const int b    = blockIdx.x;
    const int tid  = threadIdx.x;
    const int lane = tid & 31;
    const int wid  = tid >> 5;
    const float* x = xyz + (size_t)b * NPTS * 3;

    float px[16], py[16], pz[16];
#pragma unroll
    for (int i = 0; i < 16; i++) {
        int j = tid + i * 1024;
        px[i] = x[3 * j + 0];
        py[i] = x[3 * j + 1];
        pz[i] = x[3 * j + 2];
        sdist[j] = 1e10f;
    }
    if (tid == 0) sfar = 0;
    __syncthreads();

    for (int s = 0; s < NPOINT; s++) {
        const int far = sfar;
        const float cx = x[3 * far + 0];
        const float cy = x[3 * far + 1];
        const float cz = x[3 * far + 2];
        if (tid == 0) {
            fidx[b * NPOINT + s] = far;
            newxyz[(b * NPOINT + s) * 3 + 0] = cx;
            newxyz[(b * NPOINT + s) * 3 + 1] = cy;
            newxyz[(b * NPOINT + s) * 3 + 2] = cz;
        }
        unsigned long long best = 0ULL;
#pragma unroll
        for (int i = 0; i < 16; i++) {
            int j = tid + i * 1024;
            // exact square-then-add (no FMA contraction) to match XLA reduce
            float dx = __fadd_rn(px[i], -cx);
            float dy = __fadd_rn(py[i], -cy);
            float dz = __fadd_rn(pz[i], -cz);
            float m0 = __fmul_rn(dx, dx);
            float m1 = __fmul_rn(dy, dy);
            float m2 = __fmul_rn(dz, dz);
            float d  = __fadd_rn(__fadd_rn(m0, m1), m2);
            float dm = fminf(sdist[j], d);
            sdist[j] = dm;
            // max key with smallest-index tiebreak (argmax returns first)
            unsigned long long key =
                ((unsigned long long)__float_as_uint(dm) << 32) |
                (unsigned long long)(0xFFFFFFFFu - (unsigned)j);
            if (key > best) best = key;
        }
#pragma unroll
        for (int o = 16; o > 0; o >>= 1) {
            unsigned long long v = __shfl_xor_sync(0xFFFFFFFFu, best, o);
            if (v > best) best = v;
        }
        if (lane == 0) swarp[wid] = best;
        __syncthreads();
        if (wid == 0) {
            unsigned long long v = swarp[lane];
#pragma unroll
            for (int o = 16; o > 0; o >>= 1) {
                unsigned long long u = __shfl_xor_sync(0xFFFFFFFFu, v, o);
                if (u > v) v = u;
            }
            if (lane == 0)
                sfar = (int)(0xFFFFFFFFu - (unsigned)(v & 0xFFFFFFFFULL));
        }
        __syncthreads();
    }
}

// ---------------- ball query + gather + feature build: one warp per center ----------------
__global__ __launch_bounds__(256)
void ballq_feat_kernel(const float* __restrict__ xyz,
                       const float* __restrict__ points,
                       const float* __restrict__ newxyz,
                       float* __restrict__ feat0)
{
    const float R2 = (float)(0.2 * 0.2);
    const int warp = threadIdx.x >> 5;
    const int lane = threadIdx.x & 31;
    const int gw   = blockIdx.x * 8 + warp;     // 0..8191 center id
    const int b    = gw >> 10;

    const float* x = xyz + (size_t)b * NPTS * 3;
    const float cx = newxyz[gw * 3 + 0];
    const float cy = newxyz[gw * 3 + 1];
    const float cz = newxyz[gw * 3 + 2];

    __shared__ int slist[8][NSAMPLE];

    int cnt = 0;
    for (int j0 = 0; j0 < NPTS; j0 += 32) {
        int j = j0 + lane;
        float dx = __fadd_rn(x[3 * j + 0], -cx);
        float dy = __fadd_rn(x[3 * j + 1], -cy);
        float dz = __fadd_rn(x[3 * j + 2], -cz);
        float d  = __fadd_rn(__fadd_rn(__fmul_rn(dx, dx), __fmul_rn(dy, dy)),
                             __fmul_rn(dz, dz));
        bool inb = !(d > R2);
        unsigned mask = __ballot_sync(0xFFFFFFFFu, inb);
        int pos = cnt + __popc(mask & ((1u << lane) - 1u));
        if (inb && pos < NSAMPLE) slist[warp][pos] = j;
        cnt += __popc(mask);
        if (cnt >= NSAMPLE) break;
    }
    __syncwarp();

    int m = cnt < NSAMPLE ? cnt : NSAMPLE;
    int idx = (lane < m) ? slist[warp][lane] : slist[warp][0];

    const float* p = points + (size_t)b * NPTS * 3;
    size_t o = (size_t)(gw * NSAMPLE + lane) * C0;
    feat0[o + 0] = x[3 * idx + 0] - cx;
    feat0[o + 1] = x[3 * idx + 1] - cy;
    feat0[o + 2] = x[3 * idx + 2] - cz;
    feat0[o + 3] = p[3 * idx + 0];
    feat0[o + 4] = p[3 * idx + 1];
    feat0[o + 5] = p[3 * idx + 2];
}

// ---------------- conv(1x1) + fused BN-stat accumulation ----------------
// Input is RAW previous-layer output; normalization of the input (scale a, shift b,
// relu) is applied on load when !FIRST. Output is raw (pre-BN) conv result.
template<int CIN, int COUT, bool FIRST>
__global__ __launch_bounds__(256)
void layer_kernel(const float* __restrict__ X, const float* __restrict__ W,
                  const float* __restrict__ Bb,
                  const float* __restrict__ sA, const float* __restrict__ sB,
                  float* __restrict__ Y,
                  double* __restrict__ gsum, double* __restrict__ gsq)
{
    __shared__ __align__(16) float Ws[COUT * CIN];
    __shared__ float Bs[COUT];
    __shared__ float sAs[CIN], sBs[CIN];
    __shared__ float ssum[COUT], ssq[COUT];

    const int tid  = threadIdx.x;
    const int lane = tid & 31;

    for (int i = tid; i < COUT * CIN; i += 256) Ws[i] = W[i];
    for (int i = tid; i < COUT; i += 256) { Bs[i] = Bb[i]; ssum[i] = 0.f; ssq[i] = 0.f; }
    if (!FIRST)
        for (int i = tid; i < CIN; i += 256) { sAs[i] = sA[i]; sBs[i] = sB[i]; }
    __syncthreads();

    const size_t n = (size_t)blockIdx.x * 256 + tid;

    float xin[CIN];
#pragma unroll
    for (int c = 0; c < CIN; c++) {
        float v = X[n * CIN + c];
        xin[c] = FIRST ? v : fmaxf(__fmaf_rn(v, sAs[c], sBs[c]), 0.f);
    }

#pragma unroll 2
    for (int o = 0; o < COUT; o++) {
        float acc = Bs[o];
        if (CIN % 4 == 0) {
            const float4* w4 = reinterpret_cast<const float4*>(Ws + o * CIN);
#pragma unroll
            for (int c = 0; c < CIN / 4; c++) {
                float4 w = w4[c];
                acc += xin[4 * c + 0] * w.x;
                acc += xin[4 * c + 1] * w.y;
                acc += xin[4 * c + 2] * w.z;
                acc += xin[4 * c + 3] * w.w;
            }
        } else {
#pragma unroll
            for (int c = 0; c < CIN; c++) acc += xin[c] * Ws[o * CIN + c];
        }
        Y[n * COUT + o] = acc;

        float s1 = acc, s2 = acc * acc;
#pragma unroll
        for (int off = 16; off > 0; off >>= 1) {
            s1 += __shfl_xor_sync(0xFFFFFFFFu, s1, off);
            s2 += __shfl_xor_sync(0xFFFFFFFFu, s2, off);
        }
        if (lane == 0) { atomicAdd(&ssum[o], s1); atomicAdd(&ssq[o], s2); }
    }
    __syncthreads();
    for (int i = tid; i < COUT; i += 256) {
        atomicAdd(&gsum[i], (double)ssum[i]);
        atomicAdd(&gsq[i],  (double)ssq[i]);
    }
}

// ---------------- BN finalize: a = g*rsig, b = be - mu*a ----------------
__global__ void finalize_kernel(const double* __restrict__ gsum,
                                const double* __restrict__ gsq,
                                const float* __restrict__ g,
                                const float* __restrict__ be,
                                float* __restrict__ sA, float* __restrict__ sB)
{
    int c = threadIdx.x;
    double mu  = gsum[c] / (double)NTOT;
    double var = gsq[c] / (double)NTOT - mu * mu;
    float rsig = rsqrtf((float)var + 1e-5f);
    float a = g[c] * rsig;
    sA[c] = a;
    sB[c] = be[c] - (float)mu * a;
}

// ---------------- final BN + ReLU + max over K ----------------
__global__ __launch_bounds__(128)
void maxpool_kernel(const float* __restrict__ act3,
                    const float* __restrict__ sA, const float* __restrict__ sB,
                    float* __restrict__ out)
{
    const int bs = blockIdx.x;          // 0..8191
    const int c  = threadIdx.x;         // 0..127
    const float a = sA[c], b = sB[c];
    size_t base = (size_t)bs * NSAMPLE * C3;
    float m = -1e30f;
#pragma unroll 8
    for (int k = 0; k < NSAMPLE; k++) {
        float v = fmaxf(__fmaf_rn(act3[base + (size_t)k * C3 + c], a, b), 0.f);
        m = fmaxf(m, v);
    }
    out[(size_t)bs * C3 + c] = m;
}

__global__ void zero_stats(double* gsum, double* gsq)
{
    int i = threadIdx.x;
    if (i < 384) { gsum[i] = 0.0; gsq[i] = 0.0; }
}

// ---------------- launch ----------------
extern "C" void kernel_launch(void* const* d_in, const int* in_sizes, int n_in,
                              void* d_out, int out_size)
{
    const float* xyz = (const float*)d_in[0];
    const float* pts = (const float*)d_in[1];
    const float* w0  = (const float*)d_in[2];
    const float* b0  = (const float*)d_in[3];
    const float* g0  = (const float*)d_in[4];
    const float* be0 = (const float*)d_in[5];
    const float* w1  = (const float*)d_in[6];
    const float* b1  = (const float*)d_in[7];
    const float* g1  = (const float*)d_in[8];
    const float* be1 = (const float*)d_in[9];
    const float* w2  = (const float*)d_in[10];
    const float* b2  = (const float*)d_in[11];
    const float* g2  = (const float*)d_in[12];
    const float* be2 = (const float*)d_in[13];

    float* out    = (float*)d_out;
    float* newxyz = out;                              // (8,1024,3)
    float* newpts = out + BATCH * NPOINT * 3;         // (8,1024,128)

    int*    fidx;  float *feat0, *act1, *act2, *act3, *sA, *sB;
    double *gsum, *gsq;
    cudaGetSymbolAddress((void**)&fidx,  g_fidx);
    cudaGetSymbolAddress((void**)&feat0, g_feat0);
    cudaGetSymbolAddress((void**)&act1,  g_act1);
    cudaGetSymbolAddress((void**)&act2,  g_act2);
    cudaGetSymbolAddress((void**)&act3,  g_act3);
    cudaGetSymbolAddress((void**)&gsum,  g_sum);
    cudaGetSymbolAddress((void**)&gsq,   g_sq);
    cudaGetSymbolAddress((void**)&sA,    g_sA);
    cudaGetSymbolAddress((void**)&sB,    g_sB);

    cudaFuncSetAttribute(fps_kernel,
                         cudaFuncAttributeMaxDynamicSharedMemorySize,
                         NPTS * sizeof(float));

    zero_stats<<<1, 384>>>(gsum, gsq);
    fps_kernel<<<BATCH, 1024, NPTS * sizeof(float)>>>(xyz, fidx, newxyz);
    ballq_feat_kernel<<<(BATCH * NPOINT) / 8, 256>>>(xyz, pts, newxyz, feat0);

    layer_kernel<C0, C1, true ><<<NTOT / 256, 256>>>(feat0, w0, b0, nullptr, nullptr,
                                                     act1, gsum + 0,   gsq + 0);
    finalize_kernel<<<1, C1>>>(gsum + 0,   gsq + 0,   g0, be0, sA + 0,   sB + 0);

    layer_kernel<C1, C2, false><<<NTOT / 256, 256>>>(act1, w1, b1, sA + 0, sB + 0,
                                                     act2, gsum + 128, gsq + 128);
    finalize_kernel<<<1, C2>>>(gsum + 128, gsq + 128, g1, be1, sA + 128, sB + 128);

    layer_kernel<C2, C3, false><<<NTOT / 256, 256>>>(act2, w2, b2, sA + 128, sB + 128,
                                                     act3, gsum + 256, gsq + 256);
    finalize_kernel<<<1, C3>>>(gsum + 256, gsq + 256, g2, be2, sA + 256, sB + 256);

    maxpool_kernel<<<BATCH * NPOINT, 128>>>(act3, sA + 256, sB + 256, newpts);
}

// round 2
// speedup vs baseline: 1.6706x; 1.6706x over previous
#include <cuda_runtime.h>
#include <cuda_bf16.h>
#include <math.h>

// ---------------- problem constants ----------------
#define BATCH   8
#define NPTS    16384
#define NPOINT  1024
#define NSAMPLE 32
#define NTOT    (BATCH * NPOINT * NSAMPLE)   // 262144 rows through the MLP
#define C0      6
#define C1      64
#define C2      64
#define C3      128

#define FPS_THREADS 512
#define FPS_PAIRS   (NPTS / (2 * FPS_THREADS))   // 16 float2-pairs per thread

// ---------------- device scratch (no allocations allowed) ----------------
__device__ float  g_feat0[(size_t)NTOT * C0];
__device__ float  g_act1[(size_t)NTOT * C1];
__device__ float  g_act2[(size_t)NTOT * C2];
__device__ float  g_act3[(size_t)NTOT * C3];
__device__ double g_sum[3 * 128];
__device__ double g_sq[3 * 128];
__device__ float  g_sA[3 * 128];
__device__ float  g_sB[3 * 128];

// ---------------- packed f32x2 helpers (Blackwell) ----------------
__device__ __forceinline__ void f2_add(unsigned long long& o,
                                       unsigned long long a, unsigned long long b) {
    asm("add.rn.f32x2 %0, %1, %2;" : "=l"(o) : "l"(a), "l"(b));
}
__device__ __forceinline__ void f2_mul(unsigned long long& o,
                                       unsigned long long a, unsigned long long b) {
    asm("mul.rn.f32x2 %0, %1, %2;" : "=l"(o) : "l"(a), "l"(b));
}
__device__ __forceinline__ unsigned long long f2_pack(float lo, float hi) {
    unsigned long long r;
    asm("mov.b64 %0, {%1, %2};" : "=l"(r) : "f"(lo), "f"(hi));
    return r;
}
__device__ __forceinline__ void f2_unpack(float& lo, float& hi, unsigned long long v) {
    asm("mov.b64 {%0, %1}, %2;" : "=f"(lo), "=f"(hi) : "l"(v));
}

// ---------------- FPS: one block per batch ----------------
// Coordinates in registers (packed pairs), min-distance array in dynamic shared.
// One __syncthreads per iteration (double-buffered per-warp bests; every warp
// redundantly performs the final reduction so no second barrier is needed).
__global__ __launch_bounds__(FPS_THREADS, 1)
void fps_kernel(const float* __restrict__ xyz, float* __restrict__ newxyz)
{
    extern __shared__ float2 sdist2[];                 // NPTS/2 float2 = 64KB
    __shared__ unsigned long long swarp[2][FPS_THREADS / 32];

    const int b    = blockIdx.x;
    const int tid  = threadIdx.x;
    const int lane = tid & 31;
    const int wid  = tid >> 5;
    const float* x = xyz + (size_t)b * NPTS * 3;

    // load coord pairs: pair index p covers points 2p, 2p+1
    unsigned long long px[FPS_PAIRS], py[FPS_PAIRS], pz[FPS_PAIRS];
#pragma unroll
    for (int i = 0; i < FPS_PAIRS; i++) {
        int p = tid + i * FPS_THREADS;
        const float2* c6 = reinterpret_cast<const float2*>(x + 6 * p);
        float2 a = c6[0], bb = c6[1], cc = c6[2];      // x0 y0 | z0 x1 | y1 z1
        px[i] = f2_pack(a.x, bb.y);
        py[i] = f2_pack(a.y, cc.x);
        pz[i] = f2_pack(bb.x, cc.y);
        sdist2[p] = make_float2(1e10f, 1e10f);
    }
    __syncthreads();

    float cx = x[0], cy = x[1], cz = x[2];             // first farthest = index 0

    for (int s = 0; s < NPOINT; s++) {
        if (tid == 0) {
            float* o = newxyz + (size_t)(b * NPOINT + s) * 3;
            o[0] = cx; o[1] = cy; o[2] = cz;
        }
        const unsigned long long ncx = f2_pack(-cx, -cx);
        const unsigned long long ncy = f2_pack(-cy, -cy);
        const unsigned long long ncz = f2_pack(-cz, -cz);

        float bestd = -1.0f;
        int   bestj = 0;
#pragma unroll
        for (int i = 0; i < FPS_PAIRS; i++) {
            int p = tid + i * FPS_THREADS;
            unsigned long long dx, dy, dz, acc;
            f2_add(dx, px[i], ncx);
            f2_add(dy, py[i], ncy);
            f2_add(dz, pz[i], ncz);
            f2_mul(dx, dx, dx);
            f2_mul(dy, dy, dy);
            f2_mul(dz, dz, dz);
            f2_add(acc, dx, dy);
            f2_add(acc, acc, dz);
            float d0, d1;
            f2_unpack(d0, d1, acc);
            float2 dd = sdist2[p];
            d0 = fminf(dd.x, d0);
            d1 = fminf(dd.y, d1);
            sdist2[p] = make_float2(d0, d1);
            if (d0 > bestd) { bestd = d0; bestj = 2 * p; }
            if (d1 > bestd) { bestd = d1; bestj = 2 * p + 1; }
        }

        // warp reduce: key = dist bits (positive floats: order-preserving) | ~j
        unsigned long long key =
            ((unsigned long long)__float_as_uint(bestd) << 32) |
            (unsigned long long)(0xFFFFFFFFu - (unsigned)bestj);
#pragma unroll
        for (int o = 16; o > 0; o >>= 1) {
            unsigned long long v = __shfl_xor_sync(0xFFFFFFFFu, key, o);
            if (v > key) key = v;
        }
        if (lane == 0) swarp[s & 1][wid] = key;
        __syncthreads();

        // every warp reduces the 16 per-warp bests (no second barrier)
        unsigned long long v = swarp[s & 1][lane & 15];
#pragma unroll
        for (int o = 8; o > 0; o >>= 1) {
            unsigned long long u = __shfl_xor_sync(0xFFFFFFFFu, v, o);
            if (u > v) v = u;
        }
        int far = (int)(0xFFFFFFFFu - (unsigned)(v & 0xFFFFFFFFULL));
        cx = __ldg(x + 3 * far + 0);
        cy = __ldg(x + 3 * far + 1);
        cz = __ldg(x + 3 * far + 2);
    }
}

// ---------------- ball query + gather + feature build: one warp per center ----------------
__global__ __launch_bounds__(256)
void ballq_feat_kernel(const float* __restrict__ xyz,
                       const float* __restrict__ points,
                       const float* __restrict__ newxyz,
                       float* __restrict__ feat0)
{
    const float R2 = (float)(0.2 * 0.2);
    const int warp = threadIdx.x >> 5;
    const int lane = threadIdx.x & 31;
    const int gw   = blockIdx.x * 8 + warp;     // 0..8191 center id
    const int b    = gw >> 10;

    const float* x = xyz + (size_t)b * NPTS * 3;
    const float cx = newxyz[gw * 3 + 0];
    const float cy = newxyz[gw * 3 + 1];
    const float cz = newxyz[gw * 3 + 2];

    __shared__ int slist[8][NSAMPLE];

    int cnt = 0;
    for (int j0 = 0; j0 < NPTS; j0 += 32) {
        int j = j0 + lane;
        float dx = __fadd_rn(x[3 * j + 0], -cx);
        float dy = __fadd_rn(x[3 * j + 1], -cy);
        float dz = __fadd_rn(x[3 * j + 2], -cz);
        float d  = __fadd_rn(__fadd_rn(__fmul_rn(dx, dx), __fmul_rn(dy, dy)),
                             __fmul_rn(dz, dz));
        bool inb = !(d > R2);
        unsigned mask = __ballot_sync(0xFFFFFFFFu, inb);
        int pos = cnt + __popc(mask & ((1u << lane) - 1u));
        if (inb && pos < NSAMPLE) slist[warp][pos] = j;
        cnt += __popc(mask);
        if (cnt >= NSAMPLE) break;
    }
    __syncwarp();

    int m = cnt < NSAMPLE ? cnt : NSAMPLE;
    int idx = (lane < m) ? slist[warp][lane] : slist[warp][0];

    const float* p = points + (size_t)b * NPTS * 3;
    size_t o = (size_t)(gw * NSAMPLE + lane) * C0;
    feat0[o + 0] = x[3 * idx + 0] - cx;
    feat0[o + 1] = x[3 * idx + 1] - cy;
    feat0[o + 2] = x[3 * idx + 2] - cz;
    feat0[o + 3] = p[3 * idx + 0];
    feat0[o + 4] = p[3 * idx + 1];
    feat0[o + 5] = p[3 * idx + 2];
}

// ---------------- conv(1x1), raw output; input normalized on load when !FIRST ----------------
template<int CIN, int COUT, bool FIRST>
__global__ __launch_bounds__(256)
void layer_kernel(const float* __restrict__ X, const float* __restrict__ W,
                  const float* __restrict__ Bb,
                  const float* __restrict__ sA, const float* __restrict__ sB,
                  float* __restrict__ Y)
{
    __shared__ __align__(16) float Ws[COUT * CIN];
    __shared__ float Bs[COUT];
    __shared__ float sAs[CIN], sBs[CIN];

    const int tid = threadIdx.x;

    for (int i = tid; i < COUT * CIN; i += 256) Ws[i] = W[i];
    for (int i = tid; i < COUT; i += 256) Bs[i] = Bb[i];
    if (!FIRST)
        for (int i = tid; i < CIN; i += 256) { sAs[i] = sA[i]; sBs[i] = sB[i]; }
    __syncthreads();

    const size_t n = (size_t)blockIdx.x * 256 + tid;

    float xin[CIN];
    if (CIN % 4 == 0) {
        const float4* X4 = reinterpret_cast<const float4*>(X + n * CIN);
#pragma unroll
        for (int c4 = 0; c4 < CIN / 4; c4++) {
            float4 v = X4[c4];
            xin[4 * c4 + 0] = v.x; xin[4 * c4 + 1] = v.y;
            xin[4 * c4 + 2] = v.z; xin[4 * c4 + 3] = v.w;
        }
    } else {
#pragma unroll
        for (int c = 0; c < CIN; c++) xin[c] = X[n * CIN + c];
    }
    if (!FIRST) {
#pragma unroll
        for (int c = 0; c < CIN; c++)
            xin[c] = fmaxf(__fmaf_rn(xin[c], sAs[c], sBs[c]), 0.f);
    }

    float4* Y4 = reinterpret_cast<float4*>(Y + n * COUT);
#pragma unroll 2
    for (int og = 0; og < COUT / 4; og++) {
        float acc[4];
#pragma unroll
        for (int u = 0; u < 4; u++) acc[u] = Bs[4 * og + u];
        if (CIN % 4 == 0) {
#pragma unroll
            for (int u = 0; u < 4; u++) {
                const float4* w4 = reinterpret_cast<const float4*>(Ws + (4 * og + u) * CIN);
#pragma unroll
                for (int c = 0; c < CIN / 4; c++) {
                    float4 w = w4[c];
                    acc[u] += xin[4 * c + 0] * w.x;
                    acc[u] += xin[4 * c + 1] * w.y;
                    acc[u] += xin[4 * c + 2] * w.z;
                    acc[u] += xin[4 * c + 3] * w.w;
                }
            }
        } else {
#pragma unroll
            for (int u = 0; u < 4; u++)
#pragma unroll
                for (int c = 0; c < CIN; c++)
                    acc[u] += xin[c] * Ws[(4 * og + u) * CIN + c];
        }
        Y4[og] = make_float4(acc[0], acc[1], acc[2], acc[3]);
    }
}

// ---------------- per-channel sum / sumsq over raw activations ----------------
template<int C>
__global__ __launch_bounds__(256)
void stats_kernel(const float* __restrict__ Y,
                  double* __restrict__ gsum, double* __restrict__ gsq)
{
    __shared__ float  ssum[C];
    __shared__ double ssq[C];
    const int tid = threadIdx.x;
    for (int i = tid; i < C; i += 256) { ssum[i] = 0.f; ssq[i] = 0.0; }
    __syncthreads();

    const float4* Y4 = reinterpret_cast<const float4*>(Y);
    const size_t total4 = (size_t)NTOT * C / 4;
    const size_t stride = (size_t)gridDim.x * 256;      // 4*stride % C == 0 (C|1024)
    const size_t i0 = (size_t)blockIdx.x * 256 + tid;

    float  s0 = 0.f, s1 = 0.f, s2 = 0.f, s3 = 0.f;
    double q0 = 0.0, q1 = 0.0, q2 = 0.0, q3 = 0.0;
    for (size_t i = i0; i < total4; i += stride) {
        float4 v = Y4[i];
        s0 += v.x; s1 += v.y; s2 += v.z; s3 += v.w;
        q0 += (double)v.x * v.x; q1 += (double)v.y * v.y;
        q2 += (double)v.z * v.z; q3 += (double)v.w * v.w;
    }
    const int cb = (int)((4 * i0) % C);
    atomicAdd(&ssum[cb + 0], s0); atomicAdd(&ssq[cb + 0], q0);
    atomicAdd(&ssum[cb + 1], s1); atomicAdd(&ssq[cb + 1], q1);
    atomicAdd(&ssum[cb + 2], s2); atomicAdd(&ssq[cb + 2], q2);
    atomicAdd(&ssum[cb + 3], s3); atomicAdd(&ssq[cb + 3], q3);
    __syncthreads();
    for (int c = tid; c < C; c += 256) {
        atomicAdd(&gsum[c], (double)ssum[c]);
        atomicAdd(&gsq[c],  ssq[c]);
    }
}

// ---------------- BN finalize: a = g*rsig, b = be - mu*a ----------------
__global__ void finalize_kernel(const double* __restrict__ gsum,
                                const double* __restrict__ gsq,
                                const float* __restrict__ g,
                                const float* __restrict__ be,
                                float* __restrict__ sA, float* __restrict__ sB)
{
    int c = threadIdx.x;
    double mu  = gsum[c] / (double)NTOT;
    double var = gsq[c] / (double)NTOT - mu * mu;
    float rsig = rsqrtf((float)var + 1e-5f);
    float a = g[c] * rsig;
    sA[c] = a;
    sB[c] = be[c] - (float)mu * a;
}

// ---------------- final BN + ReLU + max over K ----------------
__global__ __launch_bounds__(128)
void maxpool_kernel(const float* __restrict__ act3,
                    const float* __restrict__ sA, const float* __restrict__ sB,
                    float* __restrict__ out)
{
    const int bs = blockIdx.x;          // 0..8191
    const int c  = threadIdx.x;         // 0..127
    const float a = sA[c], b = sB[c];
    size_t base = (size_t)bs * NSAMPLE * C3;
    float m = -1e30f;
#pragma unroll 8
    for (int k = 0; k < NSAMPLE; k++) {
        float v = fmaxf(__fmaf_rn(__ldg(act3 + base + (size_t)k * C3 + c), a, b), 0.f);
        m = fmaxf(m, v);
    }
    out[(size_t)bs * C3 + c] = m;
}

__global__ void zero_stats(double* gsum, double* gsq)
{
    int i = threadIdx.x;
    if (i < 384) { gsum[i] = 0.0; gsq[i] = 0.0; }
}

// ---------------- launch ----------------
extern "C" void kernel_launch(void* const* d_in, const int* in_sizes, int n_in,
                              void* d_out, int out_size)
{
    const float* xyz = (const float*)d_in[0];
    const float* pts = (const float*)d_in[1];
    const float* w0  = (const float*)d_in[2];
    const float* b0  = (const float*)d_in[3];
    const float* g0  = (const float*)d_in[4];
    const float* be0 = (const float*)d_in[5];
    const float* w1  = (const float*)d_in[6];
    const float* b1  = (const float*)d_in[7];
    const float* g1  = (const float*)d_in[8];
    const float* be1 = (const float*)d_in[9];
    const float* w2  = (const float*)d_in[10];
    const float* b2  = (const float*)d_in[11];
    const float* g2  = (const float*)d_in[12];
    const float* be2 = (const float*)d_in[13];

    float* out    = (float*)d_out;
    float* newxyz = out;                              // (8,1024,3)
    float* newpts = out + BATCH * NPOINT * 3;         // (8,1024,128)

    float *feat0, *act1, *act2, *act3, *sA, *sB;
    double *gsum, *gsq;
    cudaGetSymbolAddress((void**)&feat0, g_feat0);
    cudaGetSymbolAddress((void**)&act1,  g_act1);
    cudaGetSymbolAddress((void**)&act2,  g_act2);
    cudaGetSymbolAddress((void**)&act3,  g_act3);
    cudaGetSymbolAddress((void**)&gsum,  g_sum);
    cudaGetSymbolAddress((void**)&gsq,   g_sq);
    cudaGetSymbolAddress((void**)&sA,    g_sA);
    cudaGetSymbolAddress((void**)&sB,    g_sB);

    cudaFuncSetAttribute(fps_kernel,
                         cudaFuncAttributeMaxDynamicSharedMemorySize,
                         (NPTS / 2) * sizeof(float2));

    zero_stats<<<1, 384>>>(gsum, gsq);
    fps_kernel<<<BATCH, FPS_THREADS, (NPTS / 2) * sizeof(float2)>>>(xyz, newxyz);
    ballq_feat_kernel<<<(BATCH * NPOINT) / 8, 256>>>(xyz, pts, newxyz, feat0);

    layer_kernel<C0, C1, true ><<<NTOT / 256, 256>>>(feat0, w0, b0, nullptr, nullptr, act1);
    stats_kernel<C1><<<1184, 256>>>(act1, gsum + 0, gsq + 0);
    finalize_kernel<<<1, C1>>>(gsum + 0, gsq + 0, g0, be0, sA + 0, sB + 0);

    layer_kernel<C1, C2, false><<<NTOT / 256, 256>>>(act1, w1, b1, sA + 0, sB + 0, act2);
    stats_kernel<C2><<<1184, 256>>>(act2, gsum + 128, gsq + 128);
    finalize_kernel<<<1, C2>>>(gsum + 128, gsq + 128, g1, be1, sA + 128, sB + 128);

    layer_kernel<C2, C3, false><<<NTOT / 256, 256>>>(act2, w2, b2, sA + 128, sB + 128, act3);
    stats_kernel<C3><<<1184, 256>>>(act3, gsum + 256, gsq + 256);
    finalize_kernel<<<1, C3>>>(gsum + 256, gsq + 256, g2, be2, sA + 256, sB + 256);

    maxpool_kernel<<<BATCH * NPOINT, 128>>>(act3, sA + 256, sB + 256, newpts);
}